// round 11
// baseline (speedup 1.0000x reference)
#include <cuda_runtime.h>
#include <cuda_fp16.h>
#include <cstdint>

#define B_ 64
#define F_ 4
#define M_ 4096
#define D_ 1024
#define ITERS_ 15
#define NCTA_ 128
#define NHALF_ (B_ * D_ / 2)

// ---------------- device scratch ----------------
__device__ __half  g_Ch[F_ * M_ * D_];      // codebooks fp16 +-1, [f][m][d]
__device__ int8_t  g_Cti[F_ * D_ * M_];     // transposed int8 codebooks, [f][d][m]
__device__ __half  g_G[F_ * D_ * D_];       // (C^T C)/2 fp16, [f][d1][d2]
__device__ __half  g_est[2][F_ * B_ * D_];  // ping-pong estimates, [f][b][d]
__device__ __half  g_ne[F_ * B_ * D_];      // unbound estimates, [f][b][d]
__device__ __half  g_inp[B_ * D_];          // input +-1
__device__ int     g_diff[ITERS_];
__device__ int     g_amax[B_ * F_];
__device__ unsigned g_count;

__device__ __forceinline__ __half sgnh(float x) {
    return __float2half(x >= 0.f ? 1.f : -1.f);
}

__device__ __forceinline__ void mma16816(float* c, const unsigned* a, unsigned b0, unsigned b1) {
    asm volatile(
        "mma.sync.aligned.m16n8k16.row.col.f32.f16.f16.f32 "
        "{%0,%1,%2,%3}, {%4,%5,%6,%7}, {%8,%9}, {%0,%1,%2,%3};\n"
        : "+f"(c[0]), "+f"(c[1]), "+f"(c[2]), "+f"(c[3])
        : "r"(a[0]), "r"(a[1]), "r"(a[2]), "r"(a[3]), "r"(b0), "r"(b1));
}

__device__ __forceinline__ void imma16832(int* c, const unsigned* a, unsigned b0, unsigned b1) {
    asm volatile(
        "mma.sync.aligned.m16n8k32.row.col.s32.s8.s8.s32 "
        "{%0,%1,%2,%3}, {%4,%5,%6,%7}, {%8,%9}, {%0,%1,%2,%3};\n"
        : "+r"(c[0]), "+r"(c[1]), "+r"(c[2]), "+r"(c[3])
        : "r"(a[0]), "r"(a[1]), "r"(a[2]), "r"(a[3]), "r"(b0), "r"(b1));
}

__device__ __forceinline__ void ldsm4(unsigned& r0, unsigned& r1, unsigned& r2, unsigned& r3,
                                      unsigned addr) {
    asm volatile("ldmatrix.sync.aligned.m8n8.x4.shared.b16 {%0,%1,%2,%3}, [%4];\n"
                 : "=r"(r0), "=r"(r1), "=r"(r2), "=r"(r3)
                 : "r"(addr));
}

__device__ __forceinline__ unsigned sptr(const void* p) {
    return (unsigned)__cvta_generic_to_shared(p);
}

#define CP_ASYNC16(s, g) \
    asm volatile("cp.async.ca.shared.global [%0], [%1], 16;\n" ::"r"(s), "l"(g))
#define CP_COMMIT asm volatile("cp.async.commit_group;\n")
#define CP_WAIT(n) asm volatile("cp.async.wait_group %0;\n" ::"n"(n))

// software global barrier (1 CTA/SM co-residency; thread0 fence flushes L1D)
__device__ __forceinline__ void gbar(unsigned target) {
    __syncthreads();
    if (threadIdx.x == 0) {
        __threadfence();
        atomicAdd(&g_count, 1u);
        while (*((volatile unsigned*)&g_count) < target) {}
        __threadfence();
    }
    __syncthreads();
}

// ---------------- prep ----------------
__global__ __launch_bounds__(256) void k_prep(const float4* cb, const float* inp, const float* ie) {
    int tid = blockIdx.x * blockDim.x + threadIdx.x;
    int stride = gridDim.x * blockDim.x;
    const int n = F_ * M_ * D_ / 4;
    __half2* outc = reinterpret_cast<__half2*>(g_Ch);
    for (int i = tid; i < n; i += stride) {
        float4 v = cb[i];
        outc[2 * i] = __halves2half2(sgnh(v.x), sgnh(v.y));
        outc[2 * i + 1] = __halves2half2(sgnh(v.z), sgnh(v.w));
    }
    for (int i = tid; i < B_ * D_; i += stride) g_inp[i] = sgnh(inp[i]);
    for (int i = tid; i < B_ * F_ * D_; i += stride) {
        int b = i / (F_ * D_);
        int f = (i / D_) % F_;
        int d = i % D_;
        g_est[0][(f * B_ + b) * D_ + d] = sgnh(ie[i]);
    }
    if (tid < ITERS_) g_diff[tid] = 0;
    if (tid == 0) g_count = 0;
    for (int i = tid; i < B_ * F_; i += stride) g_amax[i] = -1;
}

// ---------------- transpose + int8: Cti[f][d][m] = sign8(Ch[f][m][d]) ----------------
__global__ __launch_bounds__(256) void k_trans8() {
    __shared__ __half T[64][72];
    const int mt = blockIdx.x * 64, dt = blockIdx.y * 64, f = blockIdx.z;
    const int tid = threadIdx.x;
    const __half* src = g_Ch + (size_t)f * M_ * D_;
    int8_t* dst = g_Cti + (size_t)f * D_ * M_;
#pragma unroll
    for (int q = 0; q < 2; q++) {
        int o = tid * 2 + q;
        int r = o >> 3, seg = o & 7;
        *(uint4*)&T[r][seg * 8] = *(const uint4*)(src + (size_t)(mt + r) * D_ + dt + seg * 8);
    }
    __syncthreads();
#pragma unroll
    for (int q = 0; q < 2; q++) {
        int o = tid * 2 + q;
        int r = o >> 3, seg = o & 7;
        int8_t tmp[8];
#pragma unroll
        for (int j = 0; j < 8; j++)
            tmp[j] = (__half_as_ushort(T[seg * 8 + j][r]) & 0x8000) ? (int8_t)-1 : (int8_t)1;
        *(uint2*)(dst + (size_t)(dt + r) * M_ + mt + seg * 8) = *(uint2*)tmp;
    }
}

// ---------------- Gram via int8 IMMA: G = (C^T C)/2 ----------------
// grid (36, 4): upper-tri 128x128 tiles + mirror. K=4096, chunks of 128, 4-buffer ring.
#define G3_PAD 144                         // 128B row + 16B pad (4-bank offset/row)
#define G3_BUFB (128 * G3_PAD)             // 18432 B per stage per operand
#define G3_SMEM (8 * G3_BUFB)              // 4 stages x (A+B) = 147456 B
__global__ __launch_bounds__(256) void k_gram3() {
    extern __shared__ __align__(16) char dsm[];
    int idx = blockIdx.x;
    const int f = blockIdx.y;
    int ti = 0;
    while (idx >= 8 - ti) { idx -= 8 - ti; ti++; }
    const int tj = ti + idx;
    const int d1b = ti * 128, d2b = tj * 128;
    const int8_t* Ct = g_Cti + (size_t)f * D_ * M_;
    const int tid = threadIdx.x, lane = tid & 31, w = tid >> 5;
    const int wm = w >> 2, wn = w & 3;  // 2 x 4 warps
    const int mr = wm * 64, nc = wn * 32;

    const unsigned SAb = sptr(dsm);                 // [4][128][144]
    const unsigned SBb = SAb + 4 * G3_BUFB;         // [4][128][144]

    int acc[4][4][4];
#pragma unroll
    for (int i = 0; i < 4; i++)
#pragma unroll
        for (int j = 0; j < 4; j++)
#pragma unroll
            for (int q = 0; q < 4; q++) acc[i][j][q] = 0;

    const int r = tid & 127, op = tid >> 7;  // 128 threads load A, 128 load B
    const int8_t* srcrow = Ct + (size_t)((op ? d2b : d1b) + r) * M_;
    const unsigned mybase = (op ? SBb : SAb) + r * G3_PAD;

#define G3_LOAD(cc)                                                   \
    do {                                                              \
        unsigned sb = mybase + ((cc) & 3) * G3_BUFB;                  \
        const int8_t* s = srcrow + (size_t)(cc) * 128;                \
        _Pragma("unroll") for (int q8 = 0; q8 < 8; q8++)              \
            CP_ASYNC16(sb + q8 * 16, s + q8 * 16);                    \
        CP_COMMIT;                                                    \
    } while (0)

    G3_LOAD(0); G3_LOAD(1); G3_LOAD(2);
    const int NCH = M_ / 128;  // 32 chunks
    for (int c = 0; c < NCH; c++) {
        CP_WAIT(2);
        __syncthreads();
        const unsigned abuf = SAb + (c & 3) * G3_BUFB;
        const unsigned bbuf = SBb + (c & 3) * G3_BUFB;
#pragma unroll
        for (int ks = 0; ks < 4; ks++) {
            const int mg = lane >> 3, lr = lane & 7;
            unsigned a[4][4], bb[4][2];
            const int rowA = ((mg & 1) ? 8 : 0) + lr;
            const int bofA = ks * 32 + ((mg & 2) ? 16 : 0);
#pragma unroll
            for (int i = 0; i < 4; i++)
                ldsm4(a[i][0], a[i][1], a[i][2], a[i][3],
                      abuf + (mr + i * 16 + rowA) * G3_PAD + bofA);
            const int rowB = ((mg & 2) ? 8 : 0) + lr;
            const int bofB = ks * 32 + ((mg & 1) ? 16 : 0);
#pragma unroll
            for (int jp = 0; jp < 2; jp++) {
                unsigned r0, r1, r2, r3;
                ldsm4(r0, r1, r2, r3, bbuf + (nc + jp * 16 + rowB) * G3_PAD + bofB);
                bb[jp * 2][0] = r0; bb[jp * 2][1] = r1;
                bb[jp * 2 + 1][0] = r2; bb[jp * 2 + 1][1] = r3;
            }
#pragma unroll
            for (int i = 0; i < 4; i++)
#pragma unroll
                for (int j = 0; j < 4; j++) imma16832(acc[i][j], a[i], bb[j][0], bb[j][1]);
        }
        if (c + 3 < NCH) { G3_LOAD(c + 3); } else { CP_COMMIT; }
    }
#undef G3_LOAD

    // epilogue: G = acc/2 (exact in fp16), mirror for off-diagonal tiles
    __half* G = g_G + (size_t)f * D_ * D_;
#pragma unroll
    for (int i = 0; i < 4; i++) {
        const int r0 = d1b + mr + i * 16 + (lane >> 2);
        const int r1 = r0 + 8;
#pragma unroll
        for (int j = 0; j < 4; j++) {
            const int c0 = d2b + nc + j * 8 + (lane & 3) * 2;
            __half h0 = __float2half((float)acc[i][j][0] * 0.5f);
            __half h1 = __float2half((float)acc[i][j][1] * 0.5f);
            __half h2 = __float2half((float)acc[i][j][2] * 0.5f);
            __half h3 = __float2half((float)acc[i][j][3] * 0.5f);
            *(__half2*)(G + (size_t)r0 * D_ + c0) = __halves2half2(h0, h1);
            *(__half2*)(G + (size_t)r1 * D_ + c0) = __halves2half2(h2, h3);
            if (ti != tj) {
                G[(size_t)c0 * D_ + r0] = h0;
                G[(size_t)(c0 + 1) * D_ + r0] = h1;
                G[(size_t)c0 * D_ + r1] = h2;
                G[(size_t)(c0 + 1) * D_ + r1] = h3;
            }
        }
    }
}

// ---------------- persistent mega-kernel ----------------
// dynamic smem layout (iteration loop):
//   Gs: [32][1032] halves = 66048 B  (G slice, resident across all iterations)
//   NE: [4][64][136] halves = 4 x 17408 B
// cleanup reuses the same buffer: cAs [3][64][40], cBs [3][128][40]
#define GS_STRIDE 1032
#define NE_STRIDE 136
#define NE_BUFH (64 * NE_STRIDE)           // halves per stage
#define MG_SMEM (66048 + 4 * NE_BUFH * 2)  // 135680 B

__device__ __forceinline__ unsigned packsign(float x, float y) {
    return (x >= 0.f ? 0x3C00u : 0xBC00u) | ((y >= 0.f ? 0x3C00u : 0xBC00u) << 16);
}

__global__ __launch_bounds__(256) void k_mega(float* out, int out_size) {
    extern __shared__ __align__(16) char dsm[];
    __half* Gs = (__half*)dsm;
    __half* NEs = (__half*)(dsm + 66048);
    const unsigned GsA = sptr(Gs), NEA = sptr(NEs);

    const int tid = threadIdx.x, lane = tid & 31, w = tid >> 5;
    const int cta = blockIdx.x;
    const int f_l = cta & 3, dt = cta >> 2;
    const int d1b = dt * 32;
    const int wb = w & 3, wd = w >> 2;

    const int er = wb * 16 + (lane >> 2);
    const int ec = d1b + wd * 16 + (lane & 3) * 2;

    unsigned prev[4];
    {
        const __half* e0 = g_est[0] + (size_t)f_l * B_ * D_;
        prev[0] = *(const unsigned*)(e0 + (size_t)er * D_ + ec);
        prev[1] = *(const unsigned*)(e0 + (size_t)(er + 8) * D_ + ec);
        prev[2] = *(const unsigned*)(e0 + (size_t)er * D_ + ec + 8);
        prev[3] = *(const unsigned*)(e0 + (size_t)(er + 8) * D_ + ec + 8);
    }

    // ---- load resident G slice (32 rows x 1024) once ----
    {
        const __half* Gg = g_G + (size_t)f_l * D_ * D_;
        const int row = tid >> 3;            // 0..31
        const int so = (tid & 7) * 128;      // halves
        const __half* src = Gg + (size_t)(d1b + row) * D_ + so;
        __half* dst = Gs + row * GS_STRIDE + so;
#pragma unroll
        for (int j = 0; j < 16; j++) CP_ASYNC16(sptr(dst + j * 8), src + j * 8);
        CP_COMMIT;
        CP_WAIT(0);
        __syncthreads();
    }

    unsigned phase = 0;
    int cur = 0;

    for (int it = 0; it < ITERS_; ++it) {
        // ---- phase A: XOR unbind ----
        {
            const unsigned* inp2 = (const unsigned*)g_inp;
            const unsigned* e = (const unsigned*)g_est[cur];
            unsigned* ne = (unsigned*)g_ne;
            const int i = cta * 256 + tid;
            unsigned a0 = e[i], a1 = e[NHALF_ + i], a2 = e[2 * NHALF_ + i], a3 = e[3 * NHALF_ + i];
            unsigned X = inp2[i] ^ a0 ^ a1 ^ a2 ^ a3;
            ne[i] = X ^ a0 ^ 0x3C003C00u;
            ne[NHALF_ + i] = X ^ a1 ^ 0x3C003C00u;
            ne[2 * NHALF_ + i] = X ^ a2 ^ 0x3C003C00u;
            ne[3 * NHALF_ + i] = X ^ a3 ^ 0x3C003C00u;
        }
        phase++; gbar(NCTA_ * phase);

        // ---- phase B: upd = sign(G @ ne); G resident in smem, ne K=128-chunk 4-buf ----
        {
            float acc0[4] = {0.f, 0.f, 0.f, 0.f};
            float acc1[4] = {0.f, 0.f, 0.f, 0.f};
            const __half* NEg = g_ne + (size_t)f_l * B_ * D_;
            const int lb = tid >> 2, so = (tid & 3) * 32;  // 64 rows x (4 x 32 halves)

#define PB_ISSUE(cc)                                                                    \
    do {                                                                                \
        unsigned db = NEA + (((cc) & 3) * NE_BUFH + lb * NE_STRIDE + so) * 2;           \
        const __half* s = NEg + (size_t)lb * D_ + (cc) * 128 + so;                      \
        CP_ASYNC16(db, s); CP_ASYNC16(db + 16, s + 8);                                  \
        CP_ASYNC16(db + 32, s + 16); CP_ASYNC16(db + 48, s + 24);                       \
        CP_COMMIT;                                                                      \
    } while (0)

            PB_ISSUE(0); PB_ISSUE(1); PB_ISSUE(2);
            for (int c = 0; c < 8; c++) {
                CP_WAIT(2);
                __syncthreads();
                const unsigned nb = NEA + ((c & 3) * NE_BUFH) * 2;
#pragma unroll
                for (int ks = 0; ks < 8; ks++) {
                    const int rowA = wb * 16 + (lane & 15);
                    const int colh = ks * 16 + (lane >> 4) * 8;
                    unsigned a[4];
                    ldsm4(a[0], a[1], a[2], a[3], nb + (rowA * NE_STRIDE + colh) * 2);
                    const int rowB = wd * 16 + (lane & 15);
                    unsigned b0, b1, b2, b3;
                    ldsm4(b0, b1, b2, b3,
                          GsA + (rowB * GS_STRIDE + c * 128 + colh) * 2);
                    mma16816(acc0, a, b0, b2);
                    mma16816(acc1, a, b1, b3);
                }
                if (c + 3 < 8) { PB_ISSUE(c + 3); } else { CP_COMMIT; }
            }
#undef PB_ISSUE

            __half* enew = g_est[cur ^ 1] + (size_t)f_l * B_ * D_;
            unsigned s[4];
            s[0] = packsign(acc0[0], acc0[1]);
            s[1] = packsign(acc0[2], acc0[3]);
            s[2] = packsign(acc1[0], acc1[1]);
            s[3] = packsign(acc1[2], acc1[3]);
            *(unsigned*)(enew + (size_t)er * D_ + ec) = s[0];
            *(unsigned*)(enew + (size_t)(er + 8) * D_ + ec) = s[1];
            *(unsigned*)(enew + (size_t)er * D_ + ec + 8) = s[2];
            *(unsigned*)(enew + (size_t)(er + 8) * D_ + ec + 8) = s[3];
            bool changed = (s[0] != prev[0]) | (s[1] != prev[1]) | (s[2] != prev[2]) |
                           (s[3] != prev[3]);
            prev[0] = s[0]; prev[1] = s[1]; prev[2] = s[2]; prev[3] = s[3];
            unsigned mask = __ballot_sync(0xffffffffu, changed);
            if (lane == 0 && mask) atomicOr(&g_diff[it], 1);
        }
        phase++; gbar(NCTA_ * phase);
        int ch = g_diff[it];
        cur ^= 1;
        if (ch == 0) break;  // fixed point: remaining iterations are no-ops
    }

    // ---- cleanup: sim = est @ C^T, 64b x 128m, 3-stage pipeline (reuses dsm) ----
    {
        __half* cAs = (__half*)dsm;               // [3][64][40]
        __half* cBs = (__half*)(dsm + 15360);     // [3][128][40]
        const unsigned cAa = sptr(cAs), cBa = sptr(cBs);
        const int fc = f_l;
        const int mtb = dt * 128;
        const int wd2 = w >> 2;
        float acc[8][4];
#pragma unroll
        for (int j = 0; j < 8; j++)
#pragma unroll
            for (int q = 0; q < 4; q++) acc[j][q] = 0.f;

        const __half* A = g_est[cur] + (size_t)fc * B_ * D_;
        const __half* C = g_Ch + (size_t)fc * M_ * D_;
        const int lb = tid >> 2, seg = (tid & 3) * 8;
        const int rb2 = tid >> 1, segb = (tid & 1) * 16;

#define CL_ISSUE(cc)                                                                     \
    do {                                                                                 \
        CP_ASYNC16(cAa + (((cc) % 3) * 2560 + lb * 40 + seg) * 2,                        \
                   A + (size_t)lb * D_ + (cc) * 32 + seg);                               \
        CP_ASYNC16(cBa + (((cc) % 3) * 5120 + rb2 * 40 + segb) * 2,                      \
                   C + (size_t)(mtb + rb2) * D_ + (cc) * 32 + segb);                     \
        CP_ASYNC16(cBa + (((cc) % 3) * 5120 + rb2 * 40 + segb + 8) * 2,                  \
                   C + (size_t)(mtb + rb2) * D_ + (cc) * 32 + segb + 8);                 \
        CP_COMMIT;                                                                       \
    } while (0)

        CL_ISSUE(0); CL_ISSUE(1);
        for (int c = 0; c < 32; c++) {
            CP_WAIT(1);
            __syncthreads();
            const unsigned ab = cAa + ((c % 3) * 2560) * 2;
            const unsigned bbf = cBa + ((c % 3) * 5120) * 2;
#pragma unroll
            for (int ks = 0; ks < 2; ks++) {
                const int rowA = wb * 16 + (lane & 15);
                const int colh = ks * 16 + (lane >> 4) * 8;
                unsigned a[4];
                ldsm4(a[0], a[1], a[2], a[3], ab + (rowA * 40 + colh) * 2);
#pragma unroll
                for (int jj = 0; jj < 4; jj++) {
                    const int rowB = wd2 * 64 + jj * 16 + (lane & 15);
                    unsigned b0, b1, b2, b3;
                    ldsm4(b0, b1, b2, b3, bbf + (rowB * 40 + colh) * 2);
                    mma16816(acc[2 * jj], a, b0, b2);
                    mma16816(acc[2 * jj + 1], a, b1, b3);
                }
            }
            if (c + 2 < 32) { CL_ISSUE(c + 2); } else { CP_COMMIT; }
        }
#undef CL_ISSUE

        int best0 = -1, best1 = -1;
#pragma unroll
        for (int jj = 0; jj < 4; jj++) {
#pragma unroll
            for (int t = 0; t < 2; t++) {
                const int m0 = mtb + wd2 * 64 + jj * 16 + t * 8 + (lane & 3) * 2;
                const float* ac = acc[2 * jj + t];
#pragma unroll
                for (int q = 0; q < 2; q++) {
                    best0 = max(best0, (((int)fabsf(ac[q])) << 12) | (4095 - (m0 + q)));
                    best1 = max(best1, (((int)fabsf(ac[2 + q])) << 12) | (4095 - (m0 + q)));
                }
            }
        }
        atomicMax(&g_amax[er * F_ + fc], best0);
        atomicMax(&g_amax[(er + 8) * F_ + fc], best1);
    }
    phase++; gbar(NCTA_ * phase);

    // ---- final outputs: [outcome(256)] [est(262144)] [iters] [conv] ----
    {
        const int g = cta * 256 + tid, gs = NCTA_ * 256;
        for (int i = g; i < B_ * F_; i += gs)
            if (i < out_size) out[i] = (float)(4095 - (g_amax[i] & 4095));
        for (int i = g; i < B_ * F_ * D_; i += gs) {
            int o = B_ * F_ + i;
            if (o < out_size) {
                int b = i / (F_ * D_);
                int f = (i / D_) % F_;
                int d = i % D_;
                out[o] = __half2float(g_est[cur][(f * B_ + b) * D_ + d]);
            }
        }
        if (cta == 0 && tid == 0) {
            int iters = 0, conv = 0;
            for (int i = 0; i < ITERS_; i++) {
                if (!conv) iters++;
                if (g_diff[i] == 0) conv = 1;
            }
            int o = B_ * F_ + B_ * F_ * D_;
            if (o < out_size) out[o] = (float)iters;
            if (o + 1 < out_size) out[o + 1] = (float)conv;
        }
    }
}

extern "C" void kernel_launch(void* const* d_in, const int* in_sizes, int n_in,
                              void* d_out, int out_size) {
    const float* inp = (const float*)d_in[0];
    const float* ie  = (const float*)d_in[1];
    const float* cb  = (const float*)d_in[2];

    cudaFuncSetAttribute(k_gram3, cudaFuncAttributeMaxDynamicSharedMemorySize, G3_SMEM);
    cudaFuncSetAttribute(k_mega, cudaFuncAttributeMaxDynamicSharedMemorySize, MG_SMEM);

    k_prep<<<1024, 256>>>((const float4*)cb, inp, ie);
    k_trans8<<<dim3(M_ / 64, D_ / 64, F_), 256>>>();
    k_gram3<<<dim3(36, 4), 256, G3_SMEM>>>();
    k_mega<<<NCTA_, 256, MG_SMEM>>>((float*)d_out, out_size);
}